// round 1
// baseline (speedup 1.0000x reference)
#include <cuda_runtime.h>
#include <cuda_bf16.h>
#include <math.h>

// Problem constants
#define B_   4
#define CIN  32
#define C_   64
#define H_   128
#define W_   128
#define HW   16384
#define DG_  8
#define CPG  8
#define KK_  9
#define OCM  216   // DG*3*K*K
#define C9   576   // C*9

// ---------------- scratch (device globals; no allocation allowed) ----------
__device__ float g_x1 [B_*C_ *HW];   // conv0 out
__device__ float g_om [B_*OCM*HW];   // offset/mask conv out
__device__ float g_dcn[B_*C_ *HW];   // lrelu(deform conv) == pre == x
__device__ float g_col[B_*C9 *HW];   // deform im2col columns [b][ci*9+k][p]
__device__ float g_x0 [B_*C_ *HW];   // a0 conv out
__device__ float g_x1d[B_*C_ *HW];   // depthwise out
__device__ float g_out[B_*C_ *HW];   // dynamic-filter out (lrelu'd)
__device__ float g_s  [B_*C_];       // channel means of x0
__device__ float g_eca[B_*C_];       // eca values

// ---------------- 1: conv0 1x1, 32->64 ------------------------------------
__global__ void conv0_k(const float* __restrict__ x, const float* __restrict__ w,
                        const float* __restrict__ bias) {
    __shared__ float ws[C_*CIN];
    int tid = threadIdx.x;
    for (int i = tid; i < C_*CIN; i += 256) ws[i] = w[i];
    __syncthreads();
    int b = blockIdx.y;
    int p = blockIdx.x*256 + tid;
    const float* xb = x + (size_t)b*CIN*HW + p;
    float acc[C_];
#pragma unroll
    for (int co = 0; co < C_; co++) acc[co] = bias[co];
    for (int ci = 0; ci < CIN; ci++) {
        float v = __ldg(xb + ci*HW);
#pragma unroll
        for (int co = 0; co < C_; co++) acc[co] += ws[co*CIN+ci]*v;
    }
    float* ob = g_x1 + (size_t)b*C_*HW + p;
#pragma unroll
    for (int co = 0; co < C_; co++) ob[co*HW] = acc[co];
}

// ---------------- 2: offset/mask conv 3x3, 32->216, pad1 -------------------
#define OMCH 24
__global__ void offm_k(const float* __restrict__ in, const float* __restrict__ w,
                       const float* __restrict__ bias) {
    __shared__ float ws[OMCH*CIN*KK_];
    int tid = threadIdx.x;
    int b = blockIdx.y;
    int p = blockIdx.x*256 + tid;
    int h = p >> 7, wq = p & 127;
    const float* ib = in + (size_t)b*CIN*HW;
    float* ob = g_om + (size_t)b*OCM*HW + p;
    for (int cc = 0; cc < OCM/OMCH; cc++) {
        int co0 = cc*OMCH;
        __syncthreads();
        for (int i = tid; i < OMCH*CIN*KK_; i += 256) ws[i] = w[co0*CIN*KK_ + i];
        __syncthreads();
        float acc[OMCH];
#pragma unroll
        for (int j = 0; j < OMCH; j++) acc[j] = bias[co0+j];
        for (int ci = 0; ci < CIN; ci++) {
            const float* ic = ib + ci*HW;
            float v[KK_];
#pragma unroll
            for (int ky = 0; ky < 3; ky++) {
                int hy = h + ky - 1;
                bool oky = (hy >= 0 && hy < H_);
#pragma unroll
                for (int kx = 0; kx < 3; kx++) {
                    int wx = wq + kx - 1;
                    v[ky*3+kx] = (oky && wx >= 0 && wx < W_) ? __ldg(ic + hy*W_ + wx) : 0.f;
                }
            }
#pragma unroll
            for (int k = 0; k < KK_; k++) {
                float vk = v[k];
#pragma unroll
                for (int j = 0; j < OMCH; j++)
                    acc[j] += ws[(j*CIN+ci)*KK_ + k]*vk;
            }
        }
#pragma unroll
        for (int j = 0; j < OMCH; j++) ob[(co0+j)*HW] = acc[j];
    }
}

// ---------------- 3: deform im2col (bilinear, modulated) -------------------
__global__ void col_k() {
    int tid = threadIdx.x;
    int p = blockIdx.x*256 + tid;
    int gk = blockIdx.y;                 // g*9+k, 0..71
    int g = gk/9, k = gk%9;
    int b = blockIdx.z;
    int h = p >> 7, wq = p & 127;
    const float* omb = g_om + (size_t)b*OCM*HW;
    float dy = omb[(       g*9+k)*HW + p];
    float dx = omb[( 72 +  g*9+k)*HW + p];
    float mk = omb[(144 +  g*9+k)*HW + p];
    mk = 1.f/(1.f + expf(-mk));
    float py = dy + (float)(k/3) + (float)h - 1.f;
    float px = dx + (float)(k%3) + (float)wq - 1.f;
    float fy = floorf(py), fx = floorf(px);
    int y0 = (int)fy, x0 = (int)fx;
    float wy = py - fy, wx = px - fx;
    float w00 = (1.f-wy)*(1.f-wx)*mk;
    float w01 = (1.f-wy)*wx*mk;
    float w10 = wy*(1.f-wx)*mk;
    float w11 = wy*wx*mk;
    bool iy0 = (y0 >= 0 && y0 < H_);
    bool iy1 = (y0+1 >= 0 && y0+1 < H_);
    bool ix0 = (x0 >= 0 && x0 < W_);
    bool ix1 = (x0+1 >= 0 && x0+1 < W_);
    bool v00 = iy0 && ix0, v01 = iy0 && ix1, v10 = iy1 && ix0, v11 = iy1 && ix1;
    int i00 = y0*W_ + x0;
    const float* xb = g_x1 + (size_t)b*C_*HW + (size_t)g*CPG*HW;
    float* cb = g_col + (size_t)b*C9*HW + (size_t)(g*CPG*KK_ + k)*HW + p;
#pragma unroll
    for (int c = 0; c < CPG; c++) {
        const float* xc = xb + c*HW;
        float s = 0.f;
        if (v00) s += w00*__ldg(xc + i00);
        if (v01) s += w01*__ldg(xc + i00 + 1);
        if (v10) s += w10*__ldg(xc + i00 + W_);
        if (v11) s += w11*__ldg(xc + i00 + W_ + 1);
        cb[(size_t)c*KK_*HW] = s;
    }
}

// ---------------- 4: dcn GEMM (64 x 576) + lrelu ---------------------------
__global__ void dcngemm_k(const float* __restrict__ w, const float* __restrict__ bias) {
    __shared__ float ws[C_*64];
    int tid = threadIdx.x;
    int b = blockIdx.y;
    int p = blockIdx.x*256 + tid;
    const float* cb = g_col + (size_t)b*C9*HW + p;
    float acc[C_];
#pragma unroll
    for (int co = 0; co < C_; co++) acc[co] = bias[co];
    for (int jc = 0; jc < C9/64; jc++) {
        __syncthreads();
        for (int i = tid; i < C_*64; i += 256) {
            int co = i >> 6, j = i & 63;
            ws[i] = w[co*C9 + jc*64 + j];
        }
        __syncthreads();
#pragma unroll 8
        for (int j = 0; j < 64; j++) {
            float v = cb[(size_t)(jc*64+j)*HW];
#pragma unroll
            for (int co = 0; co < C_; co++) acc[co] += ws[co*64+j]*v;
        }
    }
    float* ob = g_dcn + (size_t)b*C_*HW + p;
#pragma unroll
    for (int co = 0; co < C_; co++) {
        float a = acc[co];
        ob[co*HW] = (a >= 0.f) ? a : 0.2f*a;
    }
}

// ---------------- shared body: conv3x3 64->64 ------------------------------
__device__ __forceinline__ void conv3x3_body(const float* __restrict__ ib,
                                             const float* __restrict__ w,
                                             const float* __restrict__ bias,
                                             float* acc, int h, int wq, int tid,
                                             float* ws) {
#pragma unroll
    for (int co = 0; co < C_; co++) acc[co] = bias[co];
    for (int cc = 0; cc < 8; cc++) {
        __syncthreads();
        for (int i = tid; i < 8*KK_*C_; i += 256) {
            int ci8 = i/(KK_*C_);
            int k   = (i/C_)%KK_;
            int co  = i & 63;
            ws[i] = w[((size_t)co*C_ + cc*8+ci8)*KK_ + k];
        }
        __syncthreads();
        for (int ci8 = 0; ci8 < 8; ci8++) {
            const float* ic = ib + (size_t)(cc*8+ci8)*HW;
            float v[KK_];
#pragma unroll
            for (int ky = 0; ky < 3; ky++) {
                int hy = h + ky - 1;
                bool oky = (hy >= 0 && hy < H_);
#pragma unroll
                for (int kx = 0; kx < 3; kx++) {
                    int wx = wq + kx - 1;
                    v[ky*3+kx] = (oky && wx >= 0 && wx < W_) ? __ldg(ic + hy*W_ + wx) : 0.f;
                }
            }
#pragma unroll
            for (int k = 0; k < KK_; k++) {
                float vk = v[k];
                const float* wr = ws + (ci8*KK_+k)*C_;
#pragma unroll
                for (int co = 0; co < C_; co++) acc[co] += wr[co]*vk;
            }
        }
    }
}

// a0: g_dcn -> g_x0
__global__ void conv_a0_k(const float* __restrict__ w, const float* __restrict__ bias) {
    __shared__ float ws[8*KK_*C_];
    int tid = threadIdx.x;
    int b = blockIdx.y;
    int p = blockIdx.x*256 + tid;
    int h = p >> 7, wq = p & 127;
    float acc[C_];
    conv3x3_body(g_dcn + (size_t)b*C_*HW, w, bias, acc, h, wq, tid, ws);
    float* ob = g_x0 + (size_t)b*C_*HW + p;
#pragma unroll
    for (int co = 0; co < C_; co++) ob[co*HW] = acc[co];
}

// fus: g_out -> d_out (+ 2*g_dcn)
__global__ void conv_fus_k(const float* __restrict__ w, const float* __restrict__ bias,
                           float* __restrict__ out) {
    __shared__ float ws[8*KK_*C_];
    int tid = threadIdx.x;
    int b = blockIdx.y;
    int p = blockIdx.x*256 + tid;
    int h = p >> 7, wq = p & 127;
    float acc[C_];
    conv3x3_body(g_out + (size_t)b*C_*HW, w, bias, acc, h, wq, tid, ws);
    const float* pr = g_dcn + (size_t)b*C_*HW + p;
    float* ob = out + (size_t)b*C_*HW + p;
#pragma unroll
    for (int co = 0; co < C_; co++) ob[co*HW] = acc[co] + 2.f*pr[co*HW];
}

// ---------------- 6: depthwise 3x3 on g_x0 -> g_x1d ------------------------
__global__ void dw_k(const float* __restrict__ w, const float* __restrict__ bias) {
    int tid = threadIdx.x;
    int c = blockIdx.y, b = blockIdx.z;
    int p = blockIdx.x*256 + tid;
    int h = p >> 7, wq = p & 127;
    const float* ic = g_x0 + ((size_t)b*C_ + c)*HW;
    float acc = bias[c];
#pragma unroll
    for (int ky = 0; ky < 3; ky++) {
        int hy = h + ky - 1;
        bool oky = (hy >= 0 && hy < H_);
#pragma unroll
        for (int kx = 0; kx < 3; kx++) {
            int wx = wq + kx - 1;
            float v = (oky && wx >= 0 && wx < W_) ? __ldg(ic + hy*W_ + wx) : 0.f;
            acc += __ldg(w + c*KK_ + ky*3+kx)*v;
        }
    }
    g_x1d[((size_t)b*C_ + c)*HW + p] = acc;
}

// ---------------- 7: per-(b,c) mean of g_x0 --------------------------------
__global__ void mean_k() {
    __shared__ float sd[256];
    int bc = blockIdx.x;
    const float* ic = g_x0 + (size_t)bc*HW;
    float s = 0.f;
    for (int i = threadIdx.x; i < HW; i += 256) s += ic[i];
    sd[threadIdx.x] = s;
    __syncthreads();
    for (int st = 128; st > 0; st >>= 1) {
        if (threadIdx.x < st) sd[threadIdx.x] += sd[threadIdx.x+st];
        __syncthreads();
    }
    if (threadIdx.x == 0) g_s[bc] = sd[0]*(1.f/(float)HW);
}

// ---------------- 8: ECA 1D conv over channels -----------------------------
__global__ void eca_k(const float* __restrict__ w2, const float* __restrict__ b2) {
    int i = threadIdx.x;
    if (i >= B_*C_) return;
    int c = i & 63;
    float sm1 = (c > 0)  ? g_s[i-1] : 0.f;
    float s0  = g_s[i];
    float sp1 = (c < 63) ? g_s[i+1] : 0.f;
    g_eca[i] = w2[0]*sm1 + w2[1]*s0 + w2[2]*sp1 + b2[0];
}

// ---------------- 9: a3 1x1 (64->576) fused w/ dynamic filter + lrelu ------
__global__ void a3filt_k(const float* __restrict__ w, const float* __restrict__ bias) {
    __shared__ float ws[8*KK_*C_];
    __shared__ float eca_s[C_];
    int tid = threadIdx.x;
    int b = blockIdx.y;
    int p = blockIdx.x*256 + tid;
    int h = p >> 7, wq = p & 127;
    if (tid < C_) eca_s[tid] = g_eca[b*C_ + tid];
    __syncthreads();
    float inp[C_];
    const float* xb = g_x1d + (size_t)b*C_*HW + p;
#pragma unroll
    for (int ci = 0; ci < C_; ci++) inp[ci] = xb[ci*HW] + eca_s[ci];
    const float* x0b = g_x0 + (size_t)b*C_*HW;
    float* ob = g_out + (size_t)b*C_*HW + p;
    for (int cc = 0; cc < 8; cc++) {
        __syncthreads();
        for (int i = tid; i < 8*KK_*C_; i += 256) ws[i] = w[(size_t)cc*8*KK_*C_ + i];
        __syncthreads();
        for (int c8 = 0; c8 < 8; c8++) {
            int c = cc*8 + c8;
            float filt[KK_];
#pragma unroll
            for (int k = 0; k < KK_; k++) filt[k] = bias[c*KK_ + k];
#pragma unroll
            for (int ci = 0; ci < C_; ci++) {
                float v = inp[ci];
#pragma unroll
                for (int k = 0; k < KK_; k++)
                    filt[k] += ws[(c8*KK_+k)*C_ + ci]*v;
            }
            const float* ic = x0b + (size_t)c*HW;
            float o = 0.f;
#pragma unroll
            for (int ky = 0; ky < 3; ky++) {
                int hy = h + ky - 1;
                bool oky = (hy >= 0 && hy < H_);
#pragma unroll
                for (int kx = 0; kx < 3; kx++) {
                    int wx = wq + kx - 1;
                    float v = (oky && wx >= 0 && wx < W_) ? __ldg(ic + hy*W_ + wx) : 0.f;
                    o += filt[ky*3+kx]*v;
                }
            }
            ob[(size_t)c*HW + p - p] = 0.f; // (dead store removed below)
            float r = (o >= 0.f) ? o : 0.2f*o;
            ob[(size_t)c*HW] = r;
        }
    }
}

// ---------------- launch ----------------------------------------------------
extern "C" void kernel_launch(void* const* d_in, const int* in_sizes, int n_in,
                              void* d_out, int out_size) {
    const float* x       = (const float*)d_in[0];
    const float* offset  = (const float*)d_in[1];
    const float* conv0_w = (const float*)d_in[2];
    const float* conv0_b = (const float*)d_in[3];
    const float* offm_w  = (const float*)d_in[4];
    const float* offm_b  = (const float*)d_in[5];
    const float* dcn_w   = (const float*)d_in[6];
    const float* dcn_b   = (const float*)d_in[7];
    const float* a0_w    = (const float*)d_in[8];
    const float* a0_b    = (const float*)d_in[9];
    const float* a1_w    = (const float*)d_in[10];
    const float* a1_b    = (const float*)d_in[11];
    const float* a2_w    = (const float*)d_in[12];
    const float* a2_b    = (const float*)d_in[13];
    const float* a3_w    = (const float*)d_in[14];
    const float* a3_b    = (const float*)d_in[15];
    const float* fus_w   = (const float*)d_in[16];
    const float* fus_b   = (const float*)d_in[17];
    float* out = (float*)d_out;

    dim3 gp(HW/256, B_);
    conv0_k  <<<gp, 256>>>(x, conv0_w, conv0_b);
    offm_k   <<<gp, 256>>>(offset, offm_w, offm_b);
    col_k    <<<dim3(HW/256, DG_*KK_, B_), 256>>>();
    dcngemm_k<<<gp, 256>>>(dcn_w, dcn_b);
    conv_a0_k<<<gp, 256>>>(a0_w, a0_b);
    dw_k     <<<dim3(HW/256, C_, B_), 256>>>(a1_w, a1_b);
    mean_k   <<<B_*C_, 256>>>();
    eca_k    <<<1, 256>>>(a2_w, a2_b);
    a3filt_k <<<gp, 256>>>(a3_w, a3_b);
    conv_fus_k<<<gp, 256>>>(fus_w, fus_b, out);
}

// round 2
// speedup vs baseline: 1.2587x; 1.2587x over previous
#include <cuda_runtime.h>
#include <cuda_bf16.h>
#include <math.h>

// Problem constants
#define B_   4
#define CIN  32
#define C_   64
#define H_   128
#define W_   128
#define HW   16384
#define DG_  8
#define CPG  8
#define KK_  9
#define OCM  216   // DG*3*K*K
#define C9   576   // C*9

// ---------------- scratch (device globals; no allocation allowed) ----------
__device__ float g_x1 [B_*C_ *HW];   // conv0 out
__device__ float g_om [B_*OCM*HW];   // offset/mask conv out
__device__ float g_dcn[B_*C_ *HW];   // lrelu(deform conv) == pre == x
__device__ float g_col[B_*C9 *HW];   // deform im2col columns [b][ci*9+k][p]
__device__ float g_x0 [B_*C_ *HW];   // a0 conv out
__device__ float g_x1d[B_*C_ *HW];   // depthwise out
__device__ float g_out[B_*C_ *HW];   // dynamic-filter out (lrelu'd)
__device__ float g_s  [B_*C_];       // channel means of x0
__device__ float g_eca[B_*C_];       // eca values

// ---------------- 1: conv0 1x1, 32->64 ------------------------------------
__global__ void __launch_bounds__(256, 2) conv0_k(
        const float* __restrict__ x, const float* __restrict__ w,
        const float* __restrict__ bias) {
    __shared__ float ws[CIN*C_];   // [ci][co] contiguous co
    int tid = threadIdx.x;
    for (int i = tid; i < C_*CIN; i += 256) {
        int ci = i >> 6, co = i & 63;
        ws[ci*C_ + co] = w[co*CIN + ci];
    }
    __syncthreads();
    int b = blockIdx.y;
    int p = blockIdx.x*256 + tid;
    const float* xb = x + (size_t)b*CIN*HW + p;
    float acc[C_];
#pragma unroll
    for (int co = 0; co < C_; co++) acc[co] = bias[co];
    for (int ci = 0; ci < CIN; ci++) {
        float v = __ldg(xb + ci*HW);
        const float4* w4 = (const float4*)(ws + ci*C_);
#pragma unroll
        for (int q = 0; q < 16; q++) {
            float4 wv = w4[q];
            acc[q*4+0] += wv.x*v; acc[q*4+1] += wv.y*v;
            acc[q*4+2] += wv.z*v; acc[q*4+3] += wv.w*v;
        }
    }
    float* ob = g_x1 + (size_t)b*C_*HW + p;
#pragma unroll
    for (int co = 0; co < C_; co++) ob[co*HW] = acc[co];
}

// ---------------- 2: offset/mask conv 3x3, 32->216, pad1 -------------------
#define OMCH 24
__global__ void __launch_bounds__(256, 2) offm_k(
        const float* __restrict__ in, const float* __restrict__ w,
        const float* __restrict__ bias) {
    __shared__ float ws[CIN*KK_*OMCH];   // [ci][k][j] contiguous j
    int tid = threadIdx.x;
    int b = blockIdx.y;
    int p = blockIdx.x*256 + tid;
    int h = p >> 7, wq = p & 127;
    const float* ib = in + (size_t)b*CIN*HW;
    float* ob = g_om + (size_t)b*OCM*HW + p;
    for (int cc = 0; cc < OCM/OMCH; cc++) {
        int co0 = cc*OMCH;
        __syncthreads();
        for (int i = tid; i < OMCH*CIN*KK_; i += 256) {
            // i = ((j*CIN)+ci)*KK + k  (source order) -> dest [ci][k][j]
            int j  = i/(CIN*KK_);
            int ci = (i/KK_)%CIN;
            int k  = i%KK_;
            ws[(ci*KK_ + k)*OMCH + j] = w[((co0+j)*CIN + ci)*KK_ + k];
        }
        __syncthreads();
        float acc[OMCH];
#pragma unroll
        for (int j = 0; j < OMCH; j++) acc[j] = bias[co0+j];
        for (int ci = 0; ci < CIN; ci++) {
            const float* ic = ib + ci*HW;
            float v[KK_];
#pragma unroll
            for (int ky = 0; ky < 3; ky++) {
                int hy = h + ky - 1;
                bool oky = (hy >= 0 && hy < H_);
#pragma unroll
                for (int kx = 0; kx < 3; kx++) {
                    int wx = wq + kx - 1;
                    v[ky*3+kx] = (oky && wx >= 0 && wx < W_) ? __ldg(ic + hy*W_ + wx) : 0.f;
                }
            }
#pragma unroll
            for (int k = 0; k < KK_; k++) {
                float vk = v[k];
                const float4* w4 = (const float4*)(ws + (ci*KK_ + k)*OMCH);
#pragma unroll
                for (int q = 0; q < 6; q++) {
                    float4 wv = w4[q];
                    acc[q*4+0] += wv.x*vk; acc[q*4+1] += wv.y*vk;
                    acc[q*4+2] += wv.z*vk; acc[q*4+3] += wv.w*vk;
                }
            }
        }
#pragma unroll
        for (int j = 0; j < OMCH; j++) ob[(co0+j)*HW] = acc[j];
    }
}

// ---------------- 3: deform im2col (bilinear, modulated) -------------------
__global__ void __launch_bounds__(256, 2) col_k() {
    int tid = threadIdx.x;
    int p = blockIdx.x*256 + tid;
    int gk = blockIdx.y;                 // g*9+k, 0..71
    int g = gk/9, k = gk%9;
    int b = blockIdx.z;
    int h = p >> 7, wq = p & 127;
    const float* omb = g_om + (size_t)b*OCM*HW;
    float dy = omb[(       g*9+k)*HW + p];
    float dx = omb[( 72 +  g*9+k)*HW + p];
    float mk = omb[(144 +  g*9+k)*HW + p];
    mk = 1.f/(1.f + expf(-mk));
    float py = dy + (float)(k/3) + (float)h - 1.f;
    float px = dx + (float)(k%3) + (float)wq - 1.f;
    float fy = floorf(py), fx = floorf(px);
    int y0 = (int)fy, x0 = (int)fx;
    float wy = py - fy, wx = px - fx;
    float w00 = (1.f-wy)*(1.f-wx)*mk;
    float w01 = (1.f-wy)*wx*mk;
    float w10 = wy*(1.f-wx)*mk;
    float w11 = wy*wx*mk;
    bool iy0 = (y0 >= 0 && y0 < H_);
    bool iy1 = (y0+1 >= 0 && y0+1 < H_);
    bool ix0 = (x0 >= 0 && x0 < W_);
    bool ix1 = (x0+1 >= 0 && x0+1 < W_);
    bool v00 = iy0 && ix0, v01 = iy0 && ix1, v10 = iy1 && ix0, v11 = iy1 && ix1;
    int i00 = y0*W_ + x0;
    const float* xb = g_x1 + (size_t)b*C_*HW + (size_t)g*CPG*HW;
    float* cb = g_col + (size_t)b*C9*HW + (size_t)(g*CPG*KK_ + k)*HW + p;
#pragma unroll
    for (int c = 0; c < CPG; c++) {
        const float* xc = xb + c*HW;
        float s = 0.f;
        if (v00) s += w00*__ldg(xc + i00);
        if (v01) s += w01*__ldg(xc + i00 + 1);
        if (v10) s += w10*__ldg(xc + i00 + W_);
        if (v11) s += w11*__ldg(xc + i00 + W_ + 1);
        cb[(size_t)c*KK_*HW] = s;
    }
}

// ---------------- 4: dcn GEMM (64 x 576) + lrelu ---------------------------
__global__ void __launch_bounds__(256, 2) dcngemm_k(
        const float* __restrict__ w, const float* __restrict__ bias) {
    __shared__ float ws[64*C_];     // [j][co] contiguous co
    int tid = threadIdx.x;
    int b = blockIdx.y;
    int p = blockIdx.x*256 + tid;
    const float* cb = g_col + (size_t)b*C9*HW + p;
    float acc[C_];
#pragma unroll
    for (int co = 0; co < C_; co++) acc[co] = bias[co];
    for (int jc = 0; jc < C9/64; jc++) {
        __syncthreads();
        for (int i = tid; i < C_*64; i += 256) {
            int j = i >> 6, co = i & 63;
            ws[i] = w[co*C9 + jc*64 + j];
        }
        __syncthreads();
#pragma unroll 4
        for (int j = 0; j < 64; j++) {
            float v = cb[(size_t)(jc*64+j)*HW];
            const float4* w4 = (const float4*)(ws + j*C_);
#pragma unroll
            for (int q = 0; q < 16; q++) {
                float4 wv = w4[q];
                acc[q*4+0] += wv.x*v; acc[q*4+1] += wv.y*v;
                acc[q*4+2] += wv.z*v; acc[q*4+3] += wv.w*v;
            }
        }
    }
    float* ob = g_dcn + (size_t)b*C_*HW + p;
#pragma unroll
    for (int co = 0; co < C_; co++) {
        float a = acc[co];
        ob[co*HW] = (a >= 0.f) ? a : 0.2f*a;
    }
}

// ---------------- shared body: conv3x3 64->64 ------------------------------
__device__ __forceinline__ void conv3x3_body(const float* __restrict__ ib,
                                             const float* __restrict__ w,
                                             const float* __restrict__ bias,
                                             float* acc, int h, int wq, int tid,
                                             float* ws) {
#pragma unroll
    for (int co = 0; co < C_; co++) acc[co] = bias[co];
    for (int cc = 0; cc < 8; cc++) {
        __syncthreads();
        for (int i = tid; i < 8*KK_*C_; i += 256) {
            int ci8 = i/(KK_*C_);
            int k   = (i/C_)%KK_;
            int co  = i & 63;
            ws[i] = w[((size_t)co*C_ + cc*8+ci8)*KK_ + k];
        }
        __syncthreads();
        for (int ci8 = 0; ci8 < 8; ci8++) {
            const float* ic = ib + (size_t)(cc*8+ci8)*HW;
            float v[KK_];
#pragma unroll
            for (int ky = 0; ky < 3; ky++) {
                int hy = h + ky - 1;
                bool oky = (hy >= 0 && hy < H_);
#pragma unroll
                for (int kx = 0; kx < 3; kx++) {
                    int wx = wq + kx - 1;
                    v[ky*3+kx] = (oky && wx >= 0 && wx < W_) ? __ldg(ic + hy*W_ + wx) : 0.f;
                }
            }
#pragma unroll
            for (int k = 0; k < KK_; k++) {
                float vk = v[k];
                const float4* w4 = (const float4*)(ws + (ci8*KK_+k)*C_);
#pragma unroll
                for (int q = 0; q < 16; q++) {
                    float4 wv = w4[q];
                    acc[q*4+0] += wv.x*vk; acc[q*4+1] += wv.y*vk;
                    acc[q*4+2] += wv.z*vk; acc[q*4+3] += wv.w*vk;
                }
            }
        }
    }
}

// a0: g_dcn -> g_x0
__global__ void __launch_bounds__(256, 2) conv_a0_k(
        const float* __restrict__ w, const float* __restrict__ bias) {
    __shared__ float ws[8*KK_*C_];
    int tid = threadIdx.x;
    int b = blockIdx.y;
    int p = blockIdx.x*256 + tid;
    int h = p >> 7, wq = p & 127;
    float acc[C_];
    conv3x3_body(g_dcn + (size_t)b*C_*HW, w, bias, acc, h, wq, tid, ws);
    float* ob = g_x0 + (size_t)b*C_*HW + p;
#pragma unroll
    for (int co = 0; co < C_; co++) ob[co*HW] = acc[co];
}

// fus: g_out -> d_out (+ 2*g_dcn)
__global__ void __launch_bounds__(256, 2) conv_fus_k(
        const float* __restrict__ w, const float* __restrict__ bias,
        float* __restrict__ out) {
    __shared__ float ws[8*KK_*C_];
    int tid = threadIdx.x;
    int b = blockIdx.y;
    int p = blockIdx.x*256 + tid;
    int h = p >> 7, wq = p & 127;
    float acc[C_];
    conv3x3_body(g_out + (size_t)b*C_*HW, w, bias, acc, h, wq, tid, ws);
    const float* pr = g_dcn + (size_t)b*C_*HW + p;
    float* ob = out + (size_t)b*C_*HW + p;
#pragma unroll
    for (int co = 0; co < C_; co++) ob[co*HW] = acc[co] + 2.f*pr[co*HW];
}

// ---------------- 6: depthwise 3x3 on g_x0 -> g_x1d ------------------------
__global__ void __launch_bounds__(256, 4) dw_k(
        const float* __restrict__ w, const float* __restrict__ bias) {
    int tid = threadIdx.x;
    int c = blockIdx.y, b = blockIdx.z;
    int p = blockIdx.x*256 + tid;
    int h = p >> 7, wq = p & 127;
    const float* ic = g_x0 + ((size_t)b*C_ + c)*HW;
    float acc = bias[c];
#pragma unroll
    for (int ky = 0; ky < 3; ky++) {
        int hy = h + ky - 1;
        bool oky = (hy >= 0 && hy < H_);
#pragma unroll
        for (int kx = 0; kx < 3; kx++) {
            int wx = wq + kx - 1;
            float v = (oky && wx >= 0 && wx < W_) ? __ldg(ic + hy*W_ + wx) : 0.f;
            acc += __ldg(w + c*KK_ + ky*3+kx)*v;
        }
    }
    g_x1d[((size_t)b*C_ + c)*HW + p] = acc;
}

// ---------------- 7: per-(b,c) mean of g_x0 --------------------------------
__global__ void mean_k() {
    __shared__ float sd[256];
    int bc = blockIdx.x;
    const float* ic = g_x0 + (size_t)bc*HW;
    float s = 0.f;
    for (int i = threadIdx.x; i < HW; i += 256) s += ic[i];
    sd[threadIdx.x] = s;
    __syncthreads();
    for (int st = 128; st > 0; st >>= 1) {
        if (threadIdx.x < st) sd[threadIdx.x] += sd[threadIdx.x+st];
        __syncthreads();
    }
    if (threadIdx.x == 0) g_s[bc] = sd[0]*(1.f/(float)HW);
}

// ---------------- 8: ECA 1D conv over channels -----------------------------
__global__ void eca_k(const float* __restrict__ w2, const float* __restrict__ b2) {
    int i = threadIdx.x;
    if (i >= B_*C_) return;
    int c = i & 63;
    float sm1 = (c > 0)  ? g_s[i-1] : 0.f;
    float s0  = g_s[i];
    float sp1 = (c < 63) ? g_s[i+1] : 0.f;
    g_eca[i] = w2[0]*sm1 + w2[1]*s0 + w2[2]*sp1 + b2[0];
}

// ---------------- 9: a3 1x1 (64->576) fused w/ dynamic filter + lrelu ------
__global__ void __launch_bounds__(256, 2) a3filt_k(
        const float* __restrict__ w, const float* __restrict__ bias) {
    __shared__ float ws[8*KK_*C_];   // [c8][k][ci] contiguous ci
    __shared__ float eca_s[C_];
    int tid = threadIdx.x;
    int b = blockIdx.y;
    int p = blockIdx.x*256 + tid;
    int h = p >> 7, wq = p & 127;
    if (tid < C_) eca_s[tid] = g_eca[b*C_ + tid];
    __syncthreads();
    float inp[C_];
    const float* xb = g_x1d + (size_t)b*C_*HW + p;
#pragma unroll
    for (int ci = 0; ci < C_; ci++) inp[ci] = xb[ci*HW] + eca_s[ci];
    const float* x0b = g_x0 + (size_t)b*C_*HW;
    float* ob = g_out + (size_t)b*C_*HW + p;
    for (int cc = 0; cc < 8; cc++) {
        __syncthreads();
        for (int i = tid; i < 8*KK_*C_; i += 256) ws[i] = w[(size_t)cc*8*KK_*C_ + i];
        __syncthreads();
        for (int c8 = 0; c8 < 8; c8++) {
            int c = cc*8 + c8;
            float filt[KK_];
#pragma unroll
            for (int k = 0; k < KK_; k++) {
                float f = bias[c*KK_ + k];
                const float4* w4 = (const float4*)(ws + (c8*KK_+k)*C_);
#pragma unroll
                for (int q = 0; q < 16; q++) {
                    float4 wv = w4[q];
                    f += wv.x*inp[q*4+0] + wv.y*inp[q*4+1]
                       + wv.z*inp[q*4+2] + wv.w*inp[q*4+3];
                }
                filt[k] = f;
            }
            const float* ic = x0b + (size_t)c*HW;
            float o = 0.f;
#pragma unroll
            for (int ky = 0; ky < 3; ky++) {
                int hy = h + ky - 1;
                bool oky = (hy >= 0 && hy < H_);
#pragma unroll
                for (int kx = 0; kx < 3; kx++) {
                    int wx = wq + kx - 1;
                    float v = (oky && wx >= 0 && wx < W_) ? __ldg(ic + hy*W_ + wx) : 0.f;
                    o += filt[ky*3+kx]*v;
                }
            }
            float r = (o >= 0.f) ? o : 0.2f*o;
            ob[(size_t)c*HW] = r;
        }
    }
}

// ---------------- launch ----------------------------------------------------
extern "C" void kernel_launch(void* const* d_in, const int* in_sizes, int n_in,
                              void* d_out, int out_size) {
    const float* x       = (const float*)d_in[0];
    const float* offset  = (const float*)d_in[1];
    const float* conv0_w = (const float*)d_in[2];
    const float* conv0_b = (const float*)d_in[3];
    const float* offm_w  = (const float*)d_in[4];
    const float* offm_b  = (const float*)d_in[5];
    const float* dcn_w   = (const float*)d_in[6];
    const float* dcn_b   = (const float*)d_in[7];
    const float* a0_w    = (const float*)d_in[8];
    const float* a0_b    = (const float*)d_in[9];
    const float* a1_w    = (const float*)d_in[10];
    const float* a1_b    = (const float*)d_in[11];
    const float* a2_w    = (const float*)d_in[12];
    const float* a2_b    = (const float*)d_in[13];
    const float* a3_w    = (const float*)d_in[14];
    const float* a3_b    = (const float*)d_in[15];
    const float* fus_w   = (const float*)d_in[16];
    const float* fus_b   = (const float*)d_in[17];
    float* out = (float*)d_out;

    dim3 gp(HW/256, B_);
    conv0_k  <<<gp, 256>>>(x, conv0_w, conv0_b);
    offm_k   <<<gp, 256>>>(offset, offm_w, offm_b);
    col_k    <<<dim3(HW/256, DG_*KK_, B_), 256>>>();
    dcngemm_k<<<gp, 256>>>(dcn_w, dcn_b);
    conv_a0_k<<<gp, 256>>>(a0_w, a0_b);
    dw_k     <<<dim3(HW/256, C_, B_), 256>>>(a1_w, a1_b);
    mean_k   <<<B_*C_, 256>>>();
    eca_k    <<<1, 256>>>(a2_w, a2_b);
    a3filt_k <<<gp, 256>>>(a3_w, a3_b);
    conv_fus_k<<<gp, 256>>>(fus_w, fus_b, out);
}

// round 3
// speedup vs baseline: 1.6166x; 1.2843x over previous
#include <cuda_runtime.h>
#include <cuda_bf16.h>
#include <math.h>

// Problem constants
#define B_   4
#define CIN  32
#define C_   64
#define H_   128
#define W_   128
#define HW   16384
#define DG_  8
#define CPG  8
#define KK_  9
#define OCM  216   // DG*3*K*K
#define C9   576   // C*9

// ---------------- scratch (device globals; no allocation allowed) ----------
__device__ float g_x1 [B_*C_ *HW];   // conv0 out
__device__ float g_om [B_*OCM*HW];   // offset/mask conv out
__device__ float g_dcn[B_*C_ *HW];   // lrelu(deform conv) == pre == x
__device__ float g_col[B_*C9 *HW];   // deform im2col columns [b][ci*9+k][p]
__device__ float g_x0 [B_*C_ *HW];   // a0 conv out
__device__ float g_x1d[B_*C_ *HW];   // depthwise out (+eca folded in)
__device__ float g_out[B_*C_ *HW];   // dynamic-filter out (lrelu'd)
__device__ float g_s  [B_*C_];       // channel means of x0
__device__ float g_eca[B_*C_];       // eca values

// ---------------- 1: conv0 1x1, 32->64 : 4px x 16co tiling ------------------
__global__ void __launch_bounds__(256, 2) conv0_k(
        const float* __restrict__ x, const float* __restrict__ w,
        const float* __restrict__ bias) {
    __shared__ __align__(16) float ws[CIN*C_];   // [ci][co]
    int tid = threadIdx.x;
    int quad = tid & 63, cg = tid >> 6;
    for (int i = tid; i < C_*CIN; i += 256) {
        int ci = i >> 6, co = i & 63;
        ws[ci*C_ + co] = w[co*CIN + ci];
    }
    __syncthreads();
    int b = blockIdx.y;
    int p0 = blockIdx.x*256 + quad*4;
    const float* xb = x + (size_t)b*CIN*HW + p0;
    float acc[64];
#pragma unroll
    for (int c = 0; c < 16; c++) {
        float bv = __ldg(bias + cg*16 + c);
        acc[c*4+0] = bv; acc[c*4+1] = bv; acc[c*4+2] = bv; acc[c*4+3] = bv;
    }
    for (int ci = 0; ci < CIN; ci++) {
        float4 v = *(const float4*)(xb + (size_t)ci*HW);
        const float4* w4 = (const float4*)(ws + ci*C_ + cg*16);
#pragma unroll
        for (int q = 0; q < 4; q++) {
            float4 wv = w4[q];
            float wr[4] = {wv.x, wv.y, wv.z, wv.w};
#pragma unroll
            for (int r = 0; r < 4; r++) {
                float wc = wr[r];
                float* a = acc + (q*4+r)*4;
                a[0] += wc*v.x; a[1] += wc*v.y; a[2] += wc*v.z; a[3] += wc*v.w;
            }
        }
    }
    float* ob = g_x1 + (size_t)b*C_*HW + p0;
#pragma unroll
    for (int c = 0; c < 16; c++)
        *(float4*)(ob + (size_t)(cg*16+c)*HW) =
            make_float4(acc[c*4+0], acc[c*4+1], acc[c*4+2], acc[c*4+3]);
}

// ---------------- 2: offset/mask conv 3x3, 32->216 : 2px x 24co -------------
#define OMCH 24
__global__ void __launch_bounds__(256, 2) offm_k(
        const float* __restrict__ in, const float* __restrict__ w,
        const float* __restrict__ bias) {
    __shared__ __align__(16) float ws[CIN*KK_*OMCH];   // [ci][k][j]
    int tid = threadIdx.x;
    int b = blockIdx.y;
    int co0 = blockIdx.z*OMCH;
    int p0 = blockIdx.x*512 + tid*2;
    int h = p0 >> 7, wq = p0 & 127;
    for (int i = tid; i < OMCH*CIN*KK_; i += 256) {
        int ci = i/(KK_*OMCH);
        int k  = (i/OMCH)%KK_;
        int j  = i%OMCH;
        ws[i] = w[((co0+j)*CIN + ci)*KK_ + k];
    }
    __syncthreads();
    const float* ib = in + (size_t)b*CIN*HW;
    float acc[OMCH*2];
#pragma unroll
    for (int j = 0; j < OMCH; j++) {
        float bv = __ldg(bias + co0 + j);
        acc[j*2+0] = bv; acc[j*2+1] = bv;
    }
    for (int ci = 0; ci < CIN; ci++) {
        const float* ic = ib + (size_t)ci*HW;
        float v[12];   // [ky][xx] cols wq-1..wq+2
#pragma unroll
        for (int ky = 0; ky < 3; ky++) {
            int hy = h + ky - 1;
            bool oy = (hy >= 0 && hy < H_);
            const float* icr = ic + hy*W_;
#pragma unroll
            for (int xx = 0; xx < 4; xx++) {
                int wx = wq - 1 + xx;
                v[ky*4+xx] = (oy && wx >= 0 && wx < W_) ? __ldg(icr + wx) : 0.f;
            }
        }
#pragma unroll
        for (int k = 0; k < KK_; k++) {
            int ky = k/3, kx = k%3;
            float v0 = v[ky*4+kx], v1 = v[ky*4+kx+1];
            const float4* w4 = (const float4*)(ws + (ci*KK_ + k)*OMCH);
#pragma unroll
            for (int q = 0; q < 6; q++) {
                float4 wv = w4[q];
                float wr[4] = {wv.x, wv.y, wv.z, wv.w};
#pragma unroll
                for (int r = 0; r < 4; r++) {
                    float wc = wr[r];
                    acc[(q*4+r)*2+0] += wc*v0;
                    acc[(q*4+r)*2+1] += wc*v1;
                }
            }
        }
    }
    float* ob = g_om + (size_t)b*OCM*HW + p0;
#pragma unroll
    for (int j = 0; j < OMCH; j++)
        *(float2*)(ob + (size_t)(co0+j)*HW) = make_float2(acc[j*2+0], acc[j*2+1]);
}

// ---------------- 3: deform im2col (bilinear, modulated) -------------------
__global__ void __launch_bounds__(256, 2) col_k() {
    int tid = threadIdx.x;
    int p = blockIdx.x*256 + tid;
    int gk = blockIdx.y;                 // g*9+k, 0..71
    int g = gk/9, k = gk%9;
    int b = blockIdx.z;
    int h = p >> 7, wq = p & 127;
    const float* omb = g_om + (size_t)b*OCM*HW;
    float dy = omb[(       g*9+k)*HW + p];
    float dx = omb[( 72 +  g*9+k)*HW + p];
    float mk = omb[(144 +  g*9+k)*HW + p];
    mk = 1.f/(1.f + expf(-mk));
    float py = dy + (float)(k/3) + (float)h - 1.f;
    float px = dx + (float)(k%3) + (float)wq - 1.f;
    float fy = floorf(py), fx = floorf(px);
    int y0 = (int)fy, x0 = (int)fx;
    float wy = py - fy, wx = px - fx;
    float w00 = (1.f-wy)*(1.f-wx)*mk;
    float w01 = (1.f-wy)*wx*mk;
    float w10 = wy*(1.f-wx)*mk;
    float w11 = wy*wx*mk;
    bool iy0 = (y0 >= 0 && y0 < H_);
    bool iy1 = (y0+1 >= 0 && y0+1 < H_);
    bool ix0 = (x0 >= 0 && x0 < W_);
    bool ix1 = (x0+1 >= 0 && x0+1 < W_);
    bool v00 = iy0 && ix0, v01 = iy0 && ix1, v10 = iy1 && ix0, v11 = iy1 && ix1;
    int i00 = y0*W_ + x0;
    const float* xb = g_x1 + (size_t)b*C_*HW + (size_t)g*CPG*HW;
    float* cb = g_col + (size_t)b*C9*HW + (size_t)(g*CPG*KK_ + k)*HW + p;
#pragma unroll
    for (int c = 0; c < CPG; c++) {
        const float* xc = xb + c*HW;
        float s = 0.f;
        if (v00) s += w00*__ldg(xc + i00);
        if (v01) s += w01*__ldg(xc + i00 + 1);
        if (v10) s += w10*__ldg(xc + i00 + W_);
        if (v11) s += w11*__ldg(xc + i00 + W_ + 1);
        cb[(size_t)c*KK_*HW] = s;
    }
}

// ---------------- 4: dcn GEMM (64x576) + lrelu : 4px x 16co ----------------
__global__ void __launch_bounds__(256, 2) dcngemm_k(
        const float* __restrict__ w, const float* __restrict__ bias) {
    __shared__ __align__(16) float ws[64*C_];     // [j][co]
    int tid = threadIdx.x;
    int quad = tid & 63, cg = tid >> 6;
    int b = blockIdx.y;
    int p0 = blockIdx.x*256 + quad*4;
    const float* cb = g_col + (size_t)b*C9*HW + p0;
    float acc[64];
#pragma unroll
    for (int c = 0; c < 16; c++) {
        float bv = __ldg(bias + cg*16 + c);
        acc[c*4+0] = bv; acc[c*4+1] = bv; acc[c*4+2] = bv; acc[c*4+3] = bv;
    }
    for (int jc = 0; jc < C9/64; jc++) {
        __syncthreads();
        for (int i = tid; i < C_*64; i += 256) {
            int j = i >> 6, co = i & 63;
            ws[i] = w[co*C9 + jc*64 + j];
        }
        __syncthreads();
#pragma unroll 4
        for (int j = 0; j < 64; j++) {
            float4 v = *(const float4*)(cb + (size_t)(jc*64+j)*HW);
            const float4* w4 = (const float4*)(ws + j*C_ + cg*16);
#pragma unroll
            for (int q = 0; q < 4; q++) {
                float4 wv = w4[q];
                float wr[4] = {wv.x, wv.y, wv.z, wv.w};
#pragma unroll
                for (int r = 0; r < 4; r++) {
                    float wc = wr[r];
                    float* a = acc + (q*4+r)*4;
                    a[0] += wc*v.x; a[1] += wc*v.y; a[2] += wc*v.z; a[3] += wc*v.w;
                }
            }
        }
    }
    float* ob = g_dcn + (size_t)b*C_*HW + p0;
#pragma unroll
    for (int c = 0; c < 16; c++) {
        float4 o;
        o.x = acc[c*4+0]; o.y = acc[c*4+1]; o.z = acc[c*4+2]; o.w = acc[c*4+3];
        o.x = (o.x >= 0.f) ? o.x : 0.2f*o.x;
        o.y = (o.y >= 0.f) ? o.y : 0.2f*o.y;
        o.z = (o.z >= 0.f) ? o.z : 0.2f*o.z;
        o.w = (o.w >= 0.f) ? o.w : 0.2f*o.w;
        *(float4*)(ob + (size_t)(cg*16+c)*HW) = o;
    }
}

// ---------------- shared body: conv3x3 64->64 : 4px x 16co -----------------
template <int FUSE>
__device__ __forceinline__ void conv3x3_v2(const float* __restrict__ ib,
                                           const float* __restrict__ w,
                                           const float* __restrict__ bias,
                                           const float* __restrict__ pre,
                                           float* __restrict__ outp,
                                           float* ws) {
    int tid = threadIdx.x;
    int quad = tid & 63, cq = tid >> 6;
    int p0 = blockIdx.x*256 + quad*4;
    int h = p0 >> 7, wq = p0 & 127;
    float acc[64];
#pragma unroll
    for (int c = 0; c < 16; c++) {
        float bv = __ldg(bias + cq*16 + c);
        acc[c*4+0] = bv; acc[c*4+1] = bv; acc[c*4+2] = bv; acc[c*4+3] = bv;
    }
    for (int cc = 0; cc < 8; cc++) {
        __syncthreads();
        for (int i = tid; i < 8*KK_*C_; i += 256) {
            int ci8 = i/(KK_*C_);
            int k   = (i/C_)%KK_;
            int co  = i & 63;
            ws[i] = w[((size_t)co*C_ + cc*8+ci8)*KK_ + k];
        }
        __syncthreads();
        for (int ci8 = 0; ci8 < 8; ci8++) {
            const float* ic = ib + (size_t)(cc*8+ci8)*HW;
            float v[18];   // [ky][xx] cols wq-1..wq+4
#pragma unroll
            for (int ky = 0; ky < 3; ky++) {
                int hy = h + ky - 1;
                bool oy = (hy >= 0 && hy < H_);
                const float* icr = ic + hy*W_;
#pragma unroll
                for (int xx = 0; xx < 6; xx++) {
                    int wx = wq - 1 + xx;
                    v[ky*6+xx] = (oy && wx >= 0 && wx < W_) ? __ldg(icr + wx) : 0.f;
                }
            }
#pragma unroll
            for (int k = 0; k < KK_; k++) {
                int ky = k/3, kx = k%3;
                const float4* w4 = (const float4*)(ws + (ci8*KK_+k)*C_ + cq*16);
                float v0 = v[ky*6+kx+0], v1 = v[ky*6+kx+1];
                float v2 = v[ky*6+kx+2], v3 = v[ky*6+kx+3];
#pragma unroll
                for (int q = 0; q < 4; q++) {
                    float4 wv = w4[q];
                    float wr[4] = {wv.x, wv.y, wv.z, wv.w};
#pragma unroll
                    for (int r = 0; r < 4; r++) {
                        float wc = wr[r];
                        float* a = acc + (q*4+r)*4;
                        a[0] += wc*v0; a[1] += wc*v1; a[2] += wc*v2; a[3] += wc*v3;
                    }
                }
            }
        }
    }
#pragma unroll
    for (int c = 0; c < 16; c++) {
        float4 o;
        o.x = acc[c*4+0]; o.y = acc[c*4+1]; o.z = acc[c*4+2]; o.w = acc[c*4+3];
        if (FUSE) {
            float4 pv = *(const float4*)(pre + (size_t)(cq*16+c)*HW + p0);
            o.x += 2.f*pv.x; o.y += 2.f*pv.y; o.z += 2.f*pv.z; o.w += 2.f*pv.w;
        }
        *(float4*)(outp + (size_t)(cq*16+c)*HW + p0) = o;
    }
}

// a0: g_dcn -> g_x0
__global__ void __launch_bounds__(256, 2) conv_a0_k(
        const float* __restrict__ w, const float* __restrict__ bias) {
    __shared__ __align__(16) float ws[8*KK_*C_];
    int b = blockIdx.y;
    conv3x3_v2<0>(g_dcn + (size_t)b*C_*HW, w, bias, nullptr,
                  g_x0 + (size_t)b*C_*HW, ws);
}

// fus: g_out -> d_out (+ 2*g_dcn)
__global__ void __launch_bounds__(256, 2) conv_fus_k(
        const float* __restrict__ w, const float* __restrict__ bias,
        float* __restrict__ out) {
    __shared__ __align__(16) float ws[8*KK_*C_];
    int b = blockIdx.y;
    conv3x3_v2<1>(g_out + (size_t)b*C_*HW, w, bias, g_dcn + (size_t)b*C_*HW,
                  out + (size_t)b*C_*HW, ws);
}

// ---------------- 6: depthwise 3x3 on g_x0 -> g_x1d (+eca) -----------------
__global__ void __launch_bounds__(256, 4) dw_k(
        const float* __restrict__ w, const float* __restrict__ bias) {
    int tid = threadIdx.x;
    int c = blockIdx.y, b = blockIdx.z;
    int p = blockIdx.x*256 + tid;
    int h = p >> 7, wq = p & 127;
    const float* ic = g_x0 + ((size_t)b*C_ + c)*HW;
    float acc = bias[c] + g_eca[b*C_ + c];
#pragma unroll
    for (int ky = 0; ky < 3; ky++) {
        int hy = h + ky - 1;
        bool oky = (hy >= 0 && hy < H_);
#pragma unroll
        for (int kx = 0; kx < 3; kx++) {
            int wx = wq + kx - 1;
            float v = (oky && wx >= 0 && wx < W_) ? __ldg(ic + hy*W_ + wx) : 0.f;
            acc += __ldg(w + c*KK_ + ky*3+kx)*v;
        }
    }
    g_x1d[((size_t)b*C_ + c)*HW + p] = acc;
}

// ---------------- 7: per-(b,c) mean of g_x0 --------------------------------
__global__ void mean_k() {
    __shared__ float sd[256];
    int bc = blockIdx.x;
    const float* ic = g_x0 + (size_t)bc*HW;
    float s = 0.f;
    for (int i = threadIdx.x; i < HW; i += 256) s += ic[i];
    sd[threadIdx.x] = s;
    __syncthreads();
    for (int st = 128; st > 0; st >>= 1) {
        if (threadIdx.x < st) sd[threadIdx.x] += sd[threadIdx.x+st];
        __syncthreads();
    }
    if (threadIdx.x == 0) g_s[bc] = sd[0]*(1.f/(float)HW);
}

// ---------------- 8: ECA 1D conv over channels -----------------------------
__global__ void eca_k(const float* __restrict__ w2, const float* __restrict__ b2) {
    int i = threadIdx.x;
    if (i >= B_*C_) return;
    int c = i & 63;
    float sm1 = (c > 0)  ? g_s[i-1] : 0.f;
    float s0  = g_s[i];
    float sp1 = (c < 63) ? g_s[i+1] : 0.f;
    g_eca[i] = w2[0]*sm1 + w2[1]*s0 + w2[2]*sp1 + b2[0];
}

// ---------------- 9: a3 1x1 (64->576) + dynamic filter + lrelu : 4px -------
__global__ void __launch_bounds__(256, 2) a3filt_k(
        const float* __restrict__ w, const float* __restrict__ bias) {
    __shared__ __align__(16) float ws[8*KK_*C_];   // [c8][k][ci]
    int tid = threadIdx.x;
    int b = blockIdx.y;
    int cc0 = blockIdx.z*2;
    int p0 = blockIdx.x*1024 + tid*4;
    int h = p0 >> 7, wq = p0 & 127;
    const float* xb  = g_x1d + (size_t)b*C_*HW + p0;
    const float* x0b = g_x0  + (size_t)b*C_*HW;
    float* ob = g_out + (size_t)b*C_*HW + p0;
    for (int cc = cc0; cc < cc0+2; cc++) {
        __syncthreads();
        for (int i = tid; i < 8*KK_*C_; i += 256) ws[i] = w[(size_t)cc*8*KK_*C_ + i];
        __syncthreads();
        for (int c8 = 0; c8 < 8; c8++) {
            int c = cc*8 + c8;
            float filt[36];   // [k][x]
#pragma unroll
            for (int k = 0; k < KK_; k++) {
                float bv = __ldg(bias + c*KK_ + k);
                filt[k*4+0] = bv; filt[k*4+1] = bv; filt[k*4+2] = bv; filt[k*4+3] = bv;
            }
#pragma unroll 4
            for (int q = 0; q < 16; q++) {
                float4 iv0 = *(const float4*)(xb + (size_t)(q*4+0)*HW);
                float4 iv1 = *(const float4*)(xb + (size_t)(q*4+1)*HW);
                float4 iv2 = *(const float4*)(xb + (size_t)(q*4+2)*HW);
                float4 iv3 = *(const float4*)(xb + (size_t)(q*4+3)*HW);
                const float4* w4 = (const float4*)(ws + (c8*KK_)*C_);
#pragma unroll
                for (int k = 0; k < KK_; k++) {
                    float4 wv = w4[k*16 + q];
                    float* f = filt + k*4;
                    f[0] += wv.x*iv0.x + wv.y*iv1.x + wv.z*iv2.x + wv.w*iv3.x;
                    f[1] += wv.x*iv0.y + wv.y*iv1.y + wv.z*iv2.y + wv.w*iv3.y;
                    f[2] += wv.x*iv0.z + wv.y*iv1.z + wv.z*iv2.z + wv.w*iv3.z;
                    f[3] += wv.x*iv0.w + wv.y*iv1.w + wv.z*iv2.w + wv.w*iv3.w;
                }
            }
            // apply 3x3 dynamic filter over x0[c]
            const float* ic = x0b + (size_t)c*HW;
            float v[18];
#pragma unroll
            for (int ky = 0; ky < 3; ky++) {
                int hy = h + ky - 1;
                bool oy = (hy >= 0 && hy < H_);
                const float* icr = ic + hy*W_;
#pragma unroll
                for (int xx = 0; xx < 6; xx++) {
                    int wx = wq - 1 + xx;
                    v[ky*6+xx] = (oy && wx >= 0 && wx < W_) ? __ldg(icr + wx) : 0.f;
                }
            }
            float o[4] = {0.f, 0.f, 0.f, 0.f};
#pragma unroll
            for (int k = 0; k < KK_; k++) {
                int ky = k/3, kx = k%3;
#pragma unroll
                for (int xx = 0; xx < 4; xx++)
                    o[xx] += filt[k*4+xx]*v[ky*6+kx+xx];
            }
            float4 r;
            r.x = (o[0] >= 0.f) ? o[0] : 0.2f*o[0];
            r.y = (o[1] >= 0.f) ? o[1] : 0.2f*o[1];
            r.z = (o[2] >= 0.f) ? o[2] : 0.2f*o[2];
            r.w = (o[3] >= 0.f) ? o[3] : 0.2f*o[3];
            *(float4*)(ob + (size_t)c*HW) = r;
        }
    }
}

// ---------------- launch ----------------------------------------------------
extern "C" void kernel_launch(void* const* d_in, const int* in_sizes, int n_in,
                              void* d_out, int out_size) {
    const float* x       = (const float*)d_in[0];
    const float* offset  = (const float*)d_in[1];
    const float* conv0_w = (const float*)d_in[2];
    const float* conv0_b = (const float*)d_in[3];
    const float* offm_w  = (const float*)d_in[4];
    const float* offm_b  = (const float*)d_in[5];
    const float* dcn_w   = (const float*)d_in[6];
    const float* dcn_b   = (const float*)d_in[7];
    const float* a0_w    = (const float*)d_in[8];
    const float* a0_b    = (const float*)d_in[9];
    const float* a1_w    = (const float*)d_in[10];
    const float* a1_b    = (const float*)d_in[11];
    const float* a2_w    = (const float*)d_in[12];
    const float* a2_b    = (const float*)d_in[13];
    const float* a3_w    = (const float*)d_in[14];
    const float* a3_b    = (const float*)d_in[15];
    const float* fus_w   = (const float*)d_in[16];
    const float* fus_b   = (const float*)d_in[17];
    float* out = (float*)d_out;

    dim3 gp(HW/256, B_);
    conv0_k  <<<gp, 256>>>(x, conv0_w, conv0_b);
    offm_k   <<<dim3(HW/512, B_, OCM/OMCH), 256>>>(offset, offm_w, offm_b);
    col_k    <<<dim3(HW/256, DG_*KK_, B_), 256>>>();
    dcngemm_k<<<gp, 256>>>(dcn_w, dcn_b);
    conv_a0_k<<<gp, 256>>>(a0_w, a0_b);
    mean_k   <<<B_*C_, 256>>>();
    eca_k    <<<1, 256>>>(a2_w, a2_b);
    dw_k     <<<dim3(HW/256, C_, B_), 256>>>(a1_w, a1_b);
    a3filt_k <<<dim3(HW/1024, B_, 4), 256>>>(a3_w, a3_b);
    conv_fus_k<<<gp, 256>>>(fus_w, fus_b, out);
}